// round 15
// baseline (speedup 1.0000x reference)
#include <cuda_runtime.h>
#include <cuda_bf16.h>

#define NB 2
#define NS 2048
#define ND 1024
#define NH 16
#define DP 64
#define MROWS (NB*NS)
#define PIT  72
#define PITW 40

typedef unsigned int   u32;
typedef unsigned short u16;

// ---------------- device scratch ------------------------------------------
__device__ __align__(16) u16 g_inhi[3*MROWS*ND];   // split q,k,v inputs
__device__ __align__(16) u16 g_inlo[3*MROWS*ND];
__device__ __align__(16) u16 g_whi[4*ND*ND];       // split Wq,Wk,Wv,Wo
__device__ __align__(16) u16 g_wlo[4*ND*ND];
__device__ __align__(16) u16 g_qhi[NB*NH*NS*DP];
__device__ __align__(16) u16 g_qlo[NB*NH*NS*DP];
__device__ __align__(16) u16 g_khi[NB*NH*NS*DP];
__device__ __align__(16) u16 g_klo[NB*NH*NS*DP];
__device__ __align__(16) u16 g_vthi[NB*NH*DP*NS];  // V^T [B,H,d,S]
__device__ __align__(16) u16 g_vtlo[NB*NH*DP*NS];
__device__ __align__(16) u16 g_athi[MROWS*ND];     // attn split [B*S, H*d]
__device__ __align__(16) u16 g_atlo[MROWS*ND];

// ---------------- helpers --------------------------------------------------
__device__ __forceinline__ void split1(float x, u16 &h, u16 &l) {
    __nv_bfloat16 hb = __float2bfloat16(x);
    h = __bfloat16_as_ushort(hb);
    l = __bfloat16_as_ushort(__float2bfloat16(x - __bfloat162float(hb)));
}
__device__ __forceinline__ u32 pck(u16 a, u16 b) { return (u32)a | ((u32)b << 16); }

__device__ __forceinline__ void mma2(float* d, const u32* a, u32 b0, u32 b1) {
    asm volatile("mma.sync.aligned.m16n8k16.row.col.f32.bf16.bf16.f32 "
        "{%0,%1,%2,%3}, {%4,%5,%6,%7}, {%8,%9}, {%0,%1,%2,%3};"
        : "+f"(d[0]), "+f"(d[1]), "+f"(d[2]), "+f"(d[3])
        : "r"(a[0]), "r"(a[1]), "r"(a[2]), "r"(a[3]), "r"(b0), "r"(b1));
}
__device__ __forceinline__ void ldsm4(u32* r, u32 addr) {
    asm volatile("ldmatrix.sync.aligned.m8n8.x4.shared.b16 {%0,%1,%2,%3}, [%4];"
        : "=r"(r[0]), "=r"(r[1]), "=r"(r[2]), "=r"(r[3]) : "r"(addr));
}

#define CP16(dst, src) \
    asm volatile("cp.async.ca.shared.global [%0], [%1], 16;" :: "r"(dst), "l"(src))
#define CP_COMMIT() asm volatile("cp.async.commit_group;" ::: "memory")
#define CP_WAIT0()  asm volatile("cp.async.wait_group 0;" ::: "memory")
#define CP_WAIT2()  asm volatile("cp.async.wait_group 2;" ::: "memory")

__device__ __forceinline__ u32 smem_u32(const void* p) {
    u32 a;
    asm("{ .reg .u64 t; cvta.to.shared.u64 t, %1; cvt.u32.u64 %0, t; }"
        : "=r"(a) : "l"(p));
    return a;
}

// =============================================================================
// Split kernel: f32 -> bf16 hi/lo, up to 4 tensors per launch.
// =============================================================================
struct SA {
    const float* s[4];
    u16* h[4];
    u16* l[4];
    int n;
    int cnt;
};
__global__ void __launch_bounds__(256)
split_many(SA a)
{
    int z = blockIdx.z;
    if (z >= a.cnt) return;
    size_t i = ((size_t)blockIdx.x * 256 + threadIdx.x) * 4;
    if (i >= (size_t)a.n) return;
    float4 v = *(const float4*)(a.s[z] + i);
    u16 h0,l0,h1,l1,h2,l2,h3,l3;
    split1(v.x,h0,l0); split1(v.y,h1,l1); split1(v.z,h2,l2); split1(v.w,h3,l3);
    *(uint2*)(a.h[z] + i) = make_uint2(pck(h0,h1), pck(h2,h3));
    *(uint2*)(a.l[z] + i) = make_uint2(pck(l0,l1), pck(l2,l3));
}

// =============================================================================
// Projection GEMM (bf16, BK=16, 4-stage cp.async pipeline, ldmatrix).
// Stage layout (24576 B each): XH 0, XL 6144, WH 12288, WL 18432; pitch 24 u16.
// =============================================================================
#define PSM 98304
#define PJPIT 24
#define PROJ_ISSUE(ck, st) do {                                              \
    const u32 bb = sb + (u32)(st) * 24576u;                                  \
    const int kk0 = (ck) * 16;                                               \
    int r_ = tid >> 1, c_ = (tid & 1) * 8;                                   \
    u32 doff = (u32)(r_ * PJPIT + c_) * 2;                                   \
    CP16(bb + doff,          Xhi + (size_t)(m0 + r_) * ND + kk0 + c_);       \
    CP16(bb + 6144u + doff,  Xlo + (size_t)(m0 + r_) * ND + kk0 + c_);       \
    CP16(bb + 12288u + doff, Whi + (size_t)(n0 + r_) * ND + kk0 + c_);       \
    CP16(bb + 18432u + doff, Wlo + (size_t)(n0 + r_) * ND + kk0 + c_);       \
} while (0)

__global__ void __launch_bounds__(256, 2)
proj_mma(const u16* __restrict__ Xhi, const u16* __restrict__ Xlo,
         const u16* __restrict__ Whi, const u16* __restrict__ Wlo,
         const float* __restrict__ bias, float* __restrict__ OutP, int mode)
{
    extern __shared__ u16 sp[];
    const u32 sb = smem_u32(sp);
    const int tid = threadIdx.x, w = tid >> 5, lane = tid & 31;
    const int g = lane >> 2, t2 = (lane & 3) * 2;
    const u32 aoff = (u32)((lane & 7) + ((lane >> 3) & 1) * 8);
    const u32 koff = (u32)((lane >> 4) * 8);
    const int wm = w >> 2, wn = w & 3;
    const int n0 = blockIdx.x * 128, m0 = blockIdx.y * 128;

    float dd[4][4][4];
    #pragma unroll
    for (int i = 0; i < 4; ++i)
        #pragma unroll
        for (int j = 0; j < 4; ++j)
            #pragma unroll
            for (int c = 0; c < 4; ++c) dd[i][j][c] = 0.f;

    PROJ_ISSUE(0, 0); CP_COMMIT();
    PROJ_ISSUE(1, 1); CP_COMMIT();
    PROJ_ISSUE(2, 2); CP_COMMIT();

    for (int kt = 0; kt < 64; ++kt) {
        CP_WAIT2();
        __syncthreads();
        if (kt + 3 < 64) PROJ_ISSUE(kt + 3, (kt + 3) & 3);
        CP_COMMIT();
        const u32 base = sb + (u32)(kt & 3) * 24576u;

        u32 ah[4][4], al[4][4], bh[2][4], bl[2][4];
        #pragma unroll
        for (int mt = 0; mt < 4; ++mt) {
            u32 ao = ((u32)(wm*64 + mt*16) + aoff) * (PJPIT*2) + koff * 2;
            ldsm4(ah[mt], base + ao);
            ldsm4(al[mt], base + 6144u + ao);
        }
        #pragma unroll
        for (int pr = 0; pr < 2; ++pr) {
            u32 bo = ((u32)(wn*32 + pr*16) + aoff) * (PJPIT*2) + koff * 2;
            ldsm4(bh[pr], base + 12288u + bo);
            ldsm4(bl[pr], base + 18432u + bo);
        }
        #pragma unroll
        for (int mt = 0; mt < 4; ++mt)
            #pragma unroll
            for (int pr = 0; pr < 2; ++pr) {
                mma2(dd[mt][pr*2],   ah[mt], bh[pr][0], bh[pr][2]);
                mma2(dd[mt][pr*2],   ah[mt], bl[pr][0], bl[pr][2]);
                mma2(dd[mt][pr*2],   al[mt], bh[pr][0], bh[pr][2]);
                mma2(dd[mt][pr*2+1], ah[mt], bh[pr][1], bh[pr][3]);
                mma2(dd[mt][pr*2+1], ah[mt], bl[pr][1], bl[pr][3]);
                mma2(dd[mt][pr*2+1], al[mt], bh[pr][1], bh[pr][3]);
            }
        __syncthreads();
    }

    #pragma unroll
    for (int mt = 0; mt < 4; ++mt) {
        int r1 = m0 + wm*64 + mt*16 + g, r2 = r1 + 8;
        #pragma unroll
        for (int nt = 0; nt < 4; ++nt) {
            int c = n0 + wn*32 + nt*8 + t2;
            float2 bv = *(const float2*)(bias + c);
            float x0 = dd[mt][nt][0] + bv.x, x1 = dd[mt][nt][1] + bv.y;
            float x2 = dd[mt][nt][2] + bv.x, x3 = dd[mt][nt][3] + bv.y;
            if (mode == 0 || mode == 1) {
                u16* dh = (mode == 0) ? g_qhi : g_khi;
                u16* dl = (mode == 0) ? g_qlo : g_klo;
                int hh = c >> 6, cd = c & 63;
                size_t i1 = ((size_t)((r1 >> 11) * NH + hh) * NS + (r1 & 2047)) * DP + cd;
                size_t i2 = ((size_t)((r2 >> 11) * NH + hh) * NS + (r2 & 2047)) * DP + cd;
                u16 h0,l0,h1,l1;
                split1(x0,h0,l0); split1(x1,h1,l1);
                *(u32*)(dh + i1) = pck(h0,h1); *(u32*)(dl + i1) = pck(l0,l1);
                split1(x2,h0,l0); split1(x3,h1,l1);
                *(u32*)(dh + i2) = pck(h0,h1); *(u32*)(dl + i2) = pck(l0,l1);
            } else if (mode == 2) {
                int hh = c >> 6, cd = c & 63;
                int tok1 = r1 & 2047, tok2 = r2 & 2047;
                size_t b1 = ((size_t)((r1 >> 11) * NH + hh) * DP + cd) * NS + tok1;
                size_t b2 = ((size_t)((r2 >> 11) * NH + hh) * DP + cd) * NS + tok2;
                u16 h0,l0,h1,l1;
                split1(x0,h0,l0); split1(x1,h1,l1);
                g_vthi[b1] = h0; g_vtlo[b1] = l0;
                g_vthi[b1 + NS] = h1; g_vtlo[b1 + NS] = l1;
                split1(x2,h0,l0); split1(x3,h1,l1);
                g_vthi[b2] = h0; g_vtlo[b2] = l0;
                g_vthi[b2 + NS] = h1; g_vtlo[b2 + NS] = l1;
            } else {
                *(float2*)(OutP + (size_t)r1 * ND + c) = make_float2(x0, x1);
                *(float2*)(OutP + (size_t)r2 * ND + c) = make_float2(x2, x3);
            }
        }
    }
}

// =============================================================================
// Fused attention v5: store-raw + register W-fragments, pipeline depth 3.
// Phase 1 smem (bytes): QH 0..18432, QL 18432..36864,
//                       K bufs 36864 + i*9216 {KH | KL +4608}, i=0..2 -> 64512
// Phase 2 (overlaid):   V bufs i*10240 {VH | VL +5120}, i=0..2 -> 30720
//                       raw bufs 30720 + i*18432 (128 x 36 f32)  -> 86016
// stats @86016 (f32 mrow 128, lrow 128) -> ASMB 87040.
// =============================================================================
#define ASMB 87040
#define AK_ISSUE(ck, st) do {                                                \
    const u32 kb_ = sb + 36864u + (u32)(st) * 9216u;                         \
    const int k0n_ = (ck) * 32;                                              \
    CP16(kb_ + (u32)(kr * PIT + kc) * 2, khi + (size_t)(k0n_ + kr) * DP + kc); \
    CP16(kb_ + 4608u + (u32)(kr * PIT + kc) * 2, klo + (size_t)(k0n_ + kr) * DP + kc); \
} while (0)

#define AVR_ISSUE(ck, st) do {                                               \
    const u32 vb_ = sb + (u32)(st) * 10240u;                                 \
    const u32 rb_ = sb + 30720u + (u32)(st) * 18432u;                        \
    const int k0n_ = (ck) * 32;                                              \
    CP16(vb_ + (u32)(vd * PITW + vc) * 2, vthi + (size_t)vd * NS + k0n_ + vc); \
    CP16(vb_ + 5120u + (u32)(vd * PITW + vc) * 2, vtlo + (size_t)vd * NS + k0n_ + vc); \
    _Pragma("unroll")                                                        \
    for (int it_ = 0; it_ < 4; ++it_) {                                      \
        int e_ = it_ * 256 + tid, r_ = e_ >> 3, sg_ = e_ & 7;                \
        CP16(rb_ + (u32)(r_ * 144 + sg_ * 16),                               \
             wrow + (size_t)r_ * NS + k0n_ + sg_ * 4);                       \
    }                                                                        \
} while (0)

__global__ void __launch_bounds__(256, 2)
attn_mma(float* __restrict__ wbuf)
{
    extern __shared__ u16 sp[];
    u16* QH = sp;
    u16* QL = sp + 9216;
    float* mrow = (float*)(sp + 43008);   // byte 86016
    float* lrow = mrow + 128;

    const u32 sb = smem_u32(sp);
    const int tid = threadIdx.x, w = tid >> 5, lane = tid & 31;
    const int g = lane >> 2, t2 = (lane & 3) * 2;
    const u32 aoff = (u32)((lane & 7) + ((lane >> 3) & 1) * 8);
    const u32 koff = (u32)((lane >> 4) * 8);
    const int h = blockIdx.x, qt = blockIdx.y, b = blockIdx.z;
    const int q0 = qt * 128;
    const int w16 = w * 16;
    const size_t hb = (size_t)(b * NH + h) * NS;
    const u16* qhi = g_qhi + (hb + q0) * DP;
    const u16* qlo = g_qlo + (hb + q0) * DP;
    const u16* khi = g_khi + hb * DP;
    const u16* klo = g_klo + hb * DP;
    const u16* vthi = g_vthi + (size_t)(b * NH + h) * DP * NS;
    const u16* vtlo = g_vtlo + (size_t)(b * NH + h) * DP * NS;
    float* wrow = wbuf + (hb + q0) * NS;

    // Q tile resident (phase 1 only)
    #pragma unroll
    for (int it = 0; it < 4; ++it) {
        int e = it * 256 + tid, r = e >> 3, c8 = (e & 7) * 8;
        *(uint4*)(QH + r * PIT + c8) = *(const uint4*)(qhi + (size_t)r * DP + c8);
        *(uint4*)(QL + r * PIT + c8) = *(const uint4*)(qlo + (size_t)r * DP + c8);
    }

    const int kr = tid >> 3, kc = (tid & 7) * 8;   // K copy: 32 rows x 64 d
    const int vd = tid >> 2, vc = (tid & 3) * 8;   // V copy: 64 d-rows x 32 keys

    const u32 aQ = ((u32)w16 + aoff) * (PIT*2) + koff * 2;
    const u32 bK0 = aoff * (PIT*2) + koff * 2;
    const u32 bK1 = (16u + aoff) * (PIT*2) + koff * 2;

    AK_ISSUE(0, 0); CP_COMMIT();
    AK_ISSUE(1, 1); CP_COMMIT();
    AK_ISSUE(2, 2); CP_COMMIT();

    float mr[2] = {-1e30f, -1e30f}, lr[2] = {0.f, 0.f};
    int st = 0;

    // ================= phase 1: QK^T once -> raw store + stats =============
    for (int kt = 0; kt < 64; ++kt) {
        CP_WAIT2();
        __syncthreads();
        const u32 sbK = sb + 36864u + (u32)st * 9216u;
        const u32 sbKL = sbK + 4608u;
        const int k0 = kt * 32;

        float dd[4][4];
        #pragma unroll
        for (int j = 0; j < 4; ++j)
            #pragma unroll
            for (int c = 0; c < 4; ++c) dd[j][c] = 0.f;

        #pragma unroll
        for (int ks = 0; ks < 4; ++ks) {
            const u32 kb = (u32)(ks * 32);
            u32 ah[4], al[4], kh01[4], kh23[4], kl01[4], kl23[4];
            ldsm4(ah, sb + aQ + kb);
            ldsm4(al, sb + 18432u + aQ + kb);
            ldsm4(kh01, sbK + bK0 + kb);
            ldsm4(kh23, sbK + bK1 + kb);
            ldsm4(kl01, sbKL + bK0 + kb);
            ldsm4(kl23, sbKL + bK1 + kb);
            mma2(dd[0], ah, kh01[0], kh01[2]); mma2(dd[0], ah, kl01[0], kl01[2]); mma2(dd[0], al, kh01[0], kh01[2]);
            mma2(dd[1], ah, kh01[1], kh01[3]); mma2(dd[1], ah, kl01[1], kl01[3]); mma2(dd[1], al, kh01[1], kh01[3]);
            mma2(dd[2], ah, kh23[0], kh23[2]); mma2(dd[2], ah, kl23[0], kl23[2]); mma2(dd[2], al, kh23[0], kh23[2]);
            mma2(dd[3], ah, kh23[1], kh23[3]); mma2(dd[3], ah, kl23[1], kl23[3]); mma2(dd[3], al, kh23[1], kh23[3]);
        }
        #pragma unroll
        for (int j = 0; j < 4; ++j)
            #pragma unroll
            for (int c = 0; c < 4; ++c) dd[j][c] *= 0.125f;

        #pragma unroll
        for (int hf = 0; hf < 2; ++hf) {
            const int row = w16 + g + hf*8;
            #pragma unroll
            for (int nt = 0; nt < 4; ++nt)
                *(float2*)(wrow + (size_t)row * NS + k0 + nt*8 + t2)
                    = make_float2(dd[nt][hf*2], dd[nt][hf*2+1]);
            float vm = dd[0][hf*2];
            #pragma unroll
            for (int nt = 0; nt < 4; ++nt)
                vm = fmaxf(vm, fmaxf(dd[nt][hf*2], dd[nt][hf*2+1]));
            vm = fmaxf(vm, __shfl_xor_sync(0xffffffffu, vm, 1));
            vm = fmaxf(vm, __shfl_xor_sync(0xffffffffu, vm, 2));
            float mnew = fmaxf(mr[hf], vm);
            float ps = 0.f;
            #pragma unroll
            for (int nt = 0; nt < 4; ++nt)
                ps += __expf(dd[nt][hf*2] - mnew) + __expf(dd[nt][hf*2+1] - mnew);
            ps += __shfl_xor_sync(0xffffffffu, ps, 1);
            ps += __shfl_xor_sync(0xffffffffu, ps, 2);
            lr[hf] = lr[hf] * __expf(mr[hf] - mnew) + ps;
            mr[hf] = mnew;
        }
        __syncthreads();
        if (kt + 3 < 64) AK_ISSUE(kt + 3, st);
        CP_COMMIT();
        st = (st == 2) ? 0 : st + 1;
    }

    // publish stats
    if ((lane & 3) == 0) {
        #pragma unroll
        for (int hf = 0; hf < 2; ++hf) {
            int row = w16 + g + hf*8;
            mrow[row] = mr[hf];
            lrow[row] = lr[hf];
        }
    }
    __syncthreads();
    if (tid < 128) lrow[tid] = 1.0f / lrow[tid];
    __syncthreads();   // phase barrier: Q/K smem dead after this point

    const float mm0 = mrow[w16 + g],     li0 = lrow[w16 + g];
    const float mm1 = mrow[w16 + g + 8], li1 = lrow[w16 + g + 8];

    CP_WAIT0();        // drain leftover phase-1 groups before overlaying
    __syncthreads();

    AVR_ISSUE(0, 0); CP_COMMIT();
    AVR_ISSUE(1, 1); CP_COMMIT();
    AVR_ISSUE(2, 2); CP_COMMIT();

    float da[8][4];
    #pragma unroll
    for (int j = 0; j < 8; ++j)
        #pragma unroll
        for (int c = 0; c < 4; ++c) da[j][c] = 0.f;

    st = 0;
    // ================= phase 2: reload raw, normalize, A.V ================
    for (int ch = 0; ch < 64; ++ch) {
        CP_WAIT2();
        __syncthreads();
        const u32 sbV = sb + (u32)st * 10240u;
        const u32 sbVL = sbV + 5120u;
        const float* rawf = (const float*)((const char*)sp + 30720u + (u32)st * 18432u);
        const int k0 = ch * 32;

        // normalize -> w gmem store + A-operand fragments in registers
        u32 awh[2][4], awl[2][4];
        #pragma unroll
        for (int nt = 0; nt < 4; ++nt) {
            #pragma unroll
            for (int hf = 0; hf < 2; ++hf) {
                const int row = w16 + g + hf*8;
                float2 rv = *(const float2*)(rawf + row * 36 + nt*8 + t2);
                const float mm = hf ? mm1 : mm0;
                const float li = hf ? li1 : li0;
                float w0 = __expf(rv.x - mm) * li;
                float w1 = __expf(rv.y - mm) * li;
                *(float2*)(wrow + (size_t)row * NS + k0 + nt*8 + t2)
                    = make_float2(w0, w1);
                u16 h0,l0,h1,l1;
                split1(w0,h0,l0); split1(w1,h1,l1);
                awh[nt >> 1][(nt & 1) * 2 + hf] = pck(h0, h1);
                awl[nt >> 1][(nt & 1) * 2 + hf] = pck(l0, l1);
            }
        }

        // A += W . V (3-term), W fragments straight from registers
        #pragma unroll
        for (int ks = 0; ks < 2; ++ks) {
            const u32 kb = (u32)(ks * 32);
            #pragma unroll
            for (int pr = 0; pr < 4; ++pr) {
                u32 vh4[4], vl4[4];
                u32 vo = ((u32)(pr*16) + aoff) * (PITW*2) + koff * 2 + kb;
                ldsm4(vh4, sbV + vo);
                ldsm4(vl4, sbVL + vo);
                mma2(da[pr*2],   awh[ks], vh4[0], vh4[2]);
                mma2(da[pr*2],   awh[ks], vl4[0], vl4[2]);
                mma2(da[pr*2],   awl[ks], vh4[0], vh4[2]);
                mma2(da[pr*2+1], awh[ks], vh4[1], vh4[3]);
                mma2(da[pr*2+1], awh[ks], vl4[1], vl4[3]);
                mma2(da[pr*2+1], awl[ks], vh4[1], vh4[3]);
            }
        }
        __syncthreads();
        if (ch + 3 < 64) AVR_ISSUE(ch + 3, st);
        CP_COMMIT();
        st = (st == 2) ? 0 : st + 1;
    }

    // epilogue: attn rows -> split bf16 [B*S, H*d]
    #pragma unroll
    for (int hf = 0; hf < 2; ++hf) {
        const int row = w16 + g + hf*8;
        size_t base2 = (size_t)(b*NS + q0 + row) * ND + h * DP;
        #pragma unroll
        for (int nt2 = 0; nt2 < 8; ++nt2) {
            u16 h0,l0,h1,l1;
            split1(da[nt2][hf*2],   h0, l0);
            split1(da[nt2][hf*2+1], h1, l1);
            *(u32*)(g_athi + base2 + nt2*8 + t2) = pck(h0, h1);
            *(u32*)(g_atlo + base2 + nt2*8 + t2) = pck(l0, l1);
        }
    }
}

// =============================================================================
extern "C" void kernel_launch(void* const* d_in, const int* in_sizes, int n_in,
                              void* d_out, int out_size)
{
    const float* q  = (const float*)d_in[0];
    const float* k  = (const float*)d_in[1];
    const float* v  = (const float*)d_in[2];
    const float* Wq = (const float*)d_in[4];
    const float* bq = (const float*)d_in[5];
    const float* Wk = (const float*)d_in[6];
    const float* bk = (const float*)d_in[7];
    const float* Wv = (const float*)d_in[8];
    const float* bv = (const float*)d_in[9];
    const float* Wo = (const float*)d_in[10];
    const float* bo = (const float*)d_in[11];

    float* out     = (float*)d_out;
    float* weights = out + (size_t)MROWS * ND;

    cudaFuncSetAttribute(proj_mma, cudaFuncAttributeMaxDynamicSharedMemorySize, PSM);
    cudaFuncSetAttribute(attn_mma, cudaFuncAttributeMaxDynamicSharedMemorySize, ASMB);

    u16 *inhi, *inlo, *whi, *wlo, *athi, *atlo;
    cudaGetSymbolAddress((void**)&inhi, g_inhi);
    cudaGetSymbolAddress((void**)&inlo, g_inlo);
    cudaGetSymbolAddress((void**)&whi, g_whi);
    cudaGetSymbolAddress((void**)&wlo, g_wlo);
    cudaGetSymbolAddress((void**)&athi, g_athi);
    cudaGetSymbolAddress((void**)&atlo, g_atlo);

    const int NIN = MROWS * ND;   // 4194304
    const int NW  = ND * ND;      // 1048576

    // split q,k,v
    SA a1;
    a1.s[0] = q; a1.s[1] = k; a1.s[2] = v; a1.s[3] = q;
    for (int i = 0; i < 4; ++i) { a1.h[i] = inhi + (size_t)i * NIN; a1.l[i] = inlo + (size_t)i * NIN; }
    a1.h[3] = inhi; a1.l[3] = inlo;
    a1.n = NIN; a1.cnt = 3;
    split_many<<<dim3(NIN / 1024, 1, 3), 256>>>(a1);

    // split Wq,Wk,Wv,Wo
    SA a2;
    a2.s[0] = Wq; a2.s[1] = Wk; a2.s[2] = Wv; a2.s[3] = Wo;
    for (int i = 0; i < 4; ++i) { a2.h[i] = whi + (size_t)i * NW; a2.l[i] = wlo + (size_t)i * NW; }
    a2.n = NW; a2.cnt = 4;
    split_many<<<dim3(NW / 1024, 1, 4), 256>>>(a2);

    dim3 gp(ND / 128, MROWS / 128);
    proj_mma<<<gp, 256, PSM>>>(inhi,              inlo,              whi,          wlo,          bq, nullptr, 0);
    proj_mma<<<gp, 256, PSM>>>(inhi + (size_t)NIN,   inlo + (size_t)NIN,   whi + (size_t)NW,   wlo + (size_t)NW,   bk, nullptr, 1);
    proj_mma<<<gp, 256, PSM>>>(inhi + (size_t)2*NIN, inlo + (size_t)2*NIN, whi + (size_t)2*NW, wlo + (size_t)2*NW, bv, nullptr, 2);

    dim3 ga(NH, NS / 128, NB);
    attn_mma<<<ga, 256, ASMB>>>(weights);

    proj_mma<<<gp, 256, PSM>>>(athi, atlo, whi + (size_t)3*NW, wlo + (size_t)3*NW, bo, out, 3);
}

// round 16
// speedup vs baseline: 1.0720x; 1.0720x over previous
#include <cuda_runtime.h>
#include <cuda_bf16.h>

#define NB 2
#define NS 2048
#define ND 1024
#define NH 16
#define DP 64
#define MROWS (NB*NS)
#define PIT  72
#define PITW 40
#define PPIT 40

typedef unsigned int   u32;
typedef unsigned short u16;

// ---------------- device scratch ------------------------------------------
__device__ __align__(16) u16 g_inhi[3*MROWS*ND];   // split q,k,v inputs
__device__ __align__(16) u16 g_inlo[3*MROWS*ND];
__device__ __align__(16) u16 g_whi[4*ND*ND];       // split Wq,Wk,Wv,Wo
__device__ __align__(16) u16 g_wlo[4*ND*ND];
__device__ __align__(16) u16 g_qhi[NB*NH*NS*DP];
__device__ __align__(16) u16 g_qlo[NB*NH*NS*DP];
__device__ __align__(16) u16 g_khi[NB*NH*NS*DP];
__device__ __align__(16) u16 g_klo[NB*NH*NS*DP];
__device__ __align__(16) u16 g_vthi[NB*NH*DP*NS];  // V^T [B,H,d,S]
__device__ __align__(16) u16 g_vtlo[NB*NH*DP*NS];
__device__ __align__(16) u16 g_athi[MROWS*ND];     // attn split [B*S, H*d]
__device__ __align__(16) u16 g_atlo[MROWS*ND];

// ---------------- helpers --------------------------------------------------
__device__ __forceinline__ void split1(float x, u16 &h, u16 &l) {
    __nv_bfloat16 hb = __float2bfloat16(x);
    h = __bfloat16_as_ushort(hb);
    l = __bfloat16_as_ushort(__float2bfloat16(x - __bfloat162float(hb)));
}
__device__ __forceinline__ u32 pck(u16 a, u16 b) { return (u32)a | ((u32)b << 16); }

__device__ __forceinline__ void mma2(float* d, const u32* a, u32 b0, u32 b1) {
    asm volatile("mma.sync.aligned.m16n8k16.row.col.f32.bf16.bf16.f32 "
        "{%0,%1,%2,%3}, {%4,%5,%6,%7}, {%8,%9}, {%0,%1,%2,%3};"
        : "+f"(d[0]), "+f"(d[1]), "+f"(d[2]), "+f"(d[3])
        : "r"(a[0]), "r"(a[1]), "r"(a[2]), "r"(a[3]), "r"(b0), "r"(b1));
}
__device__ __forceinline__ void ldsm4(u32* r, u32 addr) {
    asm volatile("ldmatrix.sync.aligned.m8n8.x4.shared.b16 {%0,%1,%2,%3}, [%4];"
        : "=r"(r[0]), "=r"(r[1]), "=r"(r[2]), "=r"(r[3]) : "r"(addr));
}

#define CP16(dst, src) \
    asm volatile("cp.async.ca.shared.global [%0], [%1], 16;" :: "r"(dst), "l"(src))
#define CP_COMMIT() asm volatile("cp.async.commit_group;" ::: "memory")
#define CP_WAIT0()  asm volatile("cp.async.wait_group 0;" ::: "memory")

__device__ __forceinline__ u32 smem_u32(const void* p) {
    u32 a;
    asm("{ .reg .u64 t; cvta.to.shared.u64 t, %1; cvt.u32.u64 %0, t; }"
        : "=r"(a) : "l"(p));
    return a;
}

// =============================================================================
// Split kernel: f32 -> bf16 hi/lo, up to 4 tensors per launch.
// =============================================================================
struct SA {
    const float* s[4];
    u16* h[4];
    u16* l[4];
    int n;
    int cnt;
};
__global__ void __launch_bounds__(256)
split_many(SA a)
{
    int z = blockIdx.z;
    if (z >= a.cnt) return;
    size_t i = ((size_t)blockIdx.x * 256 + threadIdx.x) * 4;
    if (i >= (size_t)a.n) return;
    float4 v = *(const float4*)(a.s[z] + i);
    u16 h0,l0,h1,l1,h2,l2,h3,l3;
    split1(v.x,h0,l0); split1(v.y,h1,l1); split1(v.z,h2,l2); split1(v.w,h3,l3);
    *(uint2*)(a.h[z] + i) = make_uint2(pck(h0,h1), pck(h2,h3));
    *(uint2*)(a.l[z] + i) = make_uint2(pck(l0,l1), pck(l2,l3));
}

// =============================================================================
// Projection GEMM (bf16, cp.async BK=32 double buffer, ldmatrix).
// MMA terms issued pass-major: all hi*hi, then hi*lo, then lo*hi.
// =============================================================================
#define PSM 81920
#define PROJ_ISSUE(kt, bsel) do {                                            \
    const u32 bb = sb + (u32)(bsel) * 40960u;                                \
    const int kk0 = (kt) * 32;                                               \
    _Pragma("unroll")                                                        \
    for (int it = 0; it < 2; ++it) {                                         \
        int idx = tid + it * 256; int r = idx >> 2; int c = (idx & 3) * 8;   \
        u32 doff = (u32)(r * PPIT + c) * 2;                                  \
        CP16(bb + doff,          Xhi + (size_t)(m0 + r) * ND + kk0 + c);     \
        CP16(bb + 10240 + doff,  Xlo + (size_t)(m0 + r) * ND + kk0 + c);     \
        CP16(bb + 20480 + doff,  Whi + (size_t)(n0 + r) * ND + kk0 + c);     \
        CP16(bb + 30720 + doff,  Wlo + (size_t)(n0 + r) * ND + kk0 + c);     \
    }                                                                        \
    CP_COMMIT();                                                             \
} while (0)

__global__ void __launch_bounds__(256, 2)
proj_mma(const u16* __restrict__ Xhi, const u16* __restrict__ Xlo,
         const u16* __restrict__ Whi, const u16* __restrict__ Wlo,
         const float* __restrict__ bias, float* __restrict__ OutP, int mode)
{
    extern __shared__ u16 sp[];
    const u32 sb = smem_u32(sp);
    const int tid = threadIdx.x, w = tid >> 5, lane = tid & 31;
    const int g = lane >> 2, t2 = (lane & 3) * 2;
    const u32 aoff = (u32)((lane & 7) + ((lane >> 3) & 1) * 8);
    const u32 koff = (u32)((lane >> 4) * 8);
    const int wm = w >> 2, wn = w & 3;
    const int n0 = blockIdx.x * 128, m0 = blockIdx.y * 128;

    float dd[4][4][4];
    #pragma unroll
    for (int i = 0; i < 4; ++i)
        #pragma unroll
        for (int j = 0; j < 4; ++j)
            #pragma unroll
            for (int c = 0; c < 4; ++c) dd[i][j][c] = 0.f;

    PROJ_ISSUE(0, 0);

    for (int kt = 0; kt < 32; ++kt) {
        CP_WAIT0();
        __syncthreads();
        if (kt < 31) PROJ_ISSUE(kt + 1, (kt + 1) & 1);
        const u32 base = sb + (u32)(kt & 1) * 40960u;
        #pragma unroll
        for (int ks = 0; ks < 2; ++ks) {
            const u32 kk = (u32)(ks * 16);
            u32 ah[4][4], al[4][4], bh[2][4], bl[2][4];
            #pragma unroll
            for (int mt = 0; mt < 4; ++mt) {
                u32 ao = ((u32)(wm*64 + mt*16) + aoff) * (PPIT*2) + (kk + koff) * 2;
                ldsm4(ah[mt], base + ao);
                ldsm4(al[mt], base + 10240 + ao);
            }
            #pragma unroll
            for (int pr = 0; pr < 2; ++pr) {
                u32 bo = ((u32)(wn*32 + pr*16) + aoff) * (PPIT*2) + (kk + koff) * 2;
                ldsm4(bh[pr], base + 20480 + bo);
                ldsm4(bl[pr], base + 30720 + bo);
            }
            // pass 1: hi*hi (each accumulator touched once per pass)
            #pragma unroll
            for (int mt = 0; mt < 4; ++mt)
                #pragma unroll
                for (int pr = 0; pr < 2; ++pr) {
                    mma2(dd[mt][pr*2],   ah[mt], bh[pr][0], bh[pr][2]);
                    mma2(dd[mt][pr*2+1], ah[mt], bh[pr][1], bh[pr][3]);
                }
            // pass 2: hi*lo
            #pragma unroll
            for (int mt = 0; mt < 4; ++mt)
                #pragma unroll
                for (int pr = 0; pr < 2; ++pr) {
                    mma2(dd[mt][pr*2],   ah[mt], bl[pr][0], bl[pr][2]);
                    mma2(dd[mt][pr*2+1], ah[mt], bl[pr][1], bl[pr][3]);
                }
            // pass 3: lo*hi
            #pragma unroll
            for (int mt = 0; mt < 4; ++mt)
                #pragma unroll
                for (int pr = 0; pr < 2; ++pr) {
                    mma2(dd[mt][pr*2],   al[mt], bh[pr][0], bh[pr][2]);
                    mma2(dd[mt][pr*2+1], al[mt], bh[pr][1], bh[pr][3]);
                }
        }
    }

    #pragma unroll
    for (int mt = 0; mt < 4; ++mt) {
        int r1 = m0 + wm*64 + mt*16 + g, r2 = r1 + 8;
        #pragma unroll
        for (int nt = 0; nt < 4; ++nt) {
            int c = n0 + wn*32 + nt*8 + t2;
            float2 bv = *(const float2*)(bias + c);
            float x0 = dd[mt][nt][0] + bv.x, x1 = dd[mt][nt][1] + bv.y;
            float x2 = dd[mt][nt][2] + bv.x, x3 = dd[mt][nt][3] + bv.y;
            if (mode == 0 || mode == 1) {
                u16* dh = (mode == 0) ? g_qhi : g_khi;
                u16* dl = (mode == 0) ? g_qlo : g_klo;
                int hh = c >> 6, cd = c & 63;
                size_t i1 = ((size_t)((r1 >> 11) * NH + hh) * NS + (r1 & 2047)) * DP + cd;
                size_t i2 = ((size_t)((r2 >> 11) * NH + hh) * NS + (r2 & 2047)) * DP + cd;
                u16 h0,l0,h1,l1;
                split1(x0,h0,l0); split1(x1,h1,l1);
                *(u32*)(dh + i1) = pck(h0,h1); *(u32*)(dl + i1) = pck(l0,l1);
                split1(x2,h0,l0); split1(x3,h1,l1);
                *(u32*)(dh + i2) = pck(h0,h1); *(u32*)(dl + i2) = pck(l0,l1);
            } else if (mode == 2) {
                int hh = c >> 6, cd = c & 63;
                int tok1 = r1 & 2047, tok2 = r2 & 2047;
                size_t b1 = ((size_t)((r1 >> 11) * NH + hh) * DP + cd) * NS + tok1;
                size_t b2 = ((size_t)((r2 >> 11) * NH + hh) * DP + cd) * NS + tok2;
                u16 h0,l0,h1,l1;
                split1(x0,h0,l0); split1(x1,h1,l1);
                g_vthi[b1] = h0; g_vtlo[b1] = l0;
                g_vthi[b1 + NS] = h1; g_vtlo[b1 + NS] = l1;
                split1(x2,h0,l0); split1(x3,h1,l1);
                g_vthi[b2] = h0; g_vtlo[b2] = l0;
                g_vthi[b2 + NS] = h1; g_vtlo[b2 + NS] = l1;
            } else {
                *(float2*)(OutP + (size_t)r1 * ND + c) = make_float2(x0, x1);
                *(float2*)(OutP + (size_t)r2 * ND + c) = make_float2(x2, x3);
            }
        }
    }
}

// =============================================================================
// Fused attention v4 (R14 structure): store-raw + register W-fragments,
// double-buffered cp.async, term-major MMA passes.
// Phase 1 smem (bytes): QH 0..18432, QL 18432..36864,
//                       K bufs 36864 + i*9216 {KH 4608 | KL +4608} -> 55296
// Phase 2 smem (overlaid): V bufs 0 + i*10240 {VH 5120 | VL +5120} -> 20480
//                          raw bufs 20480 + i*18432 (128 x 36 f32) -> 57344
// stats 57344..58368.  ASMB = 58368.
// =============================================================================
#define ASMB 58368
__global__ void __launch_bounds__(256, 2)
attn_mma(float* __restrict__ wbuf)
{
    extern __shared__ u16 sp[];
    u16* QH = sp;
    u16* QL = sp + 9216;
    float* mrow = (float*)(sp + 28672);   // byte 57344
    float* lrow = mrow + 128;

    const u32 sb = smem_u32(sp);
    const int tid = threadIdx.x, w = tid >> 5, lane = tid & 31;
    const int g = lane >> 2, t2 = (lane & 3) * 2;
    const u32 aoff = (u32)((lane & 7) + ((lane >> 3) & 1) * 8);
    const u32 koff = (u32)((lane >> 4) * 8);
    const int h = blockIdx.x, qt = blockIdx.y, b = blockIdx.z;
    const int q0 = qt * 128;
    const int w16 = w * 16;
    const size_t hb = (size_t)(b * NH + h) * NS;
    const u16* qhi = g_qhi + (hb + q0) * DP;
    const u16* qlo = g_qlo + (hb + q0) * DP;
    const u16* khi = g_khi + hb * DP;
    const u16* klo = g_klo + hb * DP;
    const u16* vthi = g_vthi + (size_t)(b * NH + h) * DP * NS;
    const u16* vtlo = g_vtlo + (size_t)(b * NH + h) * DP * NS;
    float* wrow = wbuf + (hb + q0) * NS;

    // Q tile resident (phase 1 only)
    #pragma unroll
    for (int it = 0; it < 4; ++it) {
        int e = it * 256 + tid, r = e >> 3, c8 = (e & 7) * 8;
        *(uint4*)(QH + r * PIT + c8) = *(const uint4*)(qhi + (size_t)r * DP + c8);
        *(uint4*)(QL + r * PIT + c8) = *(const uint4*)(qlo + (size_t)r * DP + c8);
    }

    const int kr = tid >> 3, kc = (tid & 7) * 8;   // K copy: 32 rows x 64 d
    const int vd = tid >> 2, vc = (tid & 3) * 8;   // V copy: 64 d-rows x 32 keys

    const u32 aQ = ((u32)w16 + aoff) * (PIT*2) + koff * 2;
    const u32 bK0 = aoff * (PIT*2) + koff * 2;
    const u32 bK1 = (16u + aoff) * (PIT*2) + koff * 2;

    // ---- issue K chunk 0 ----
    {
        const u32 kh0 = sb + 36864u, kl0 = kh0 + 4608u;
        CP16(kh0 + (u32)(kr * PIT + kc) * 2, khi + (size_t)kr * DP + kc);
        CP16(kl0 + (u32)(kr * PIT + kc) * 2, klo + (size_t)kr * DP + kc);
        CP_COMMIT();
    }

    float mr[2] = {-1e30f, -1e30f}, lr[2] = {0.f, 0.f};

    // ================= phase 1: QK^T once -> raw store + stats =============
    for (int kt = 0; kt < 64; ++kt) {
        CP_WAIT0();
        __syncthreads();
        if (kt < 63) {
            const u32 khb = sb + 36864u + (u32)((kt + 1) & 1) * 9216u;
            const int k0n = (kt + 1) * 32;
            CP16(khb + (u32)(kr * PIT + kc) * 2, khi + (size_t)(k0n + kr) * DP + kc);
            CP16(khb + 4608u + (u32)(kr * PIT + kc) * 2, klo + (size_t)(k0n + kr) * DP + kc);
            CP_COMMIT();
        }
        const u32 sbK = sb + 36864u + (u32)(kt & 1) * 9216u;
        const u32 sbKL = sbK + 4608u;
        const int k0 = kt * 32;

        float dd[4][4];
        #pragma unroll
        for (int j = 0; j < 4; ++j)
            #pragma unroll
            for (int c = 0; c < 4; ++c) dd[j][c] = 0.f;

        #pragma unroll
        for (int ks = 0; ks < 4; ++ks) {
            const u32 kb = (u32)(ks * 32);
            u32 ah[4], al[4], kh01[4], kh23[4], kl01[4], kl23[4];
            ldsm4(ah, sb + aQ + kb);
            ldsm4(al, sb + 18432u + aQ + kb);
            ldsm4(kh01, sbK + bK0 + kb);
            ldsm4(kh23, sbK + bK1 + kb);
            ldsm4(kl01, sbKL + bK0 + kb);
            ldsm4(kl23, sbKL + bK1 + kb);
            // term-major passes: hi*hi, hi*lo, lo*hi (sep 4 per accumulator)
            mma2(dd[0], ah, kh01[0], kh01[2]);
            mma2(dd[1], ah, kh01[1], kh01[3]);
            mma2(dd[2], ah, kh23[0], kh23[2]);
            mma2(dd[3], ah, kh23[1], kh23[3]);
            mma2(dd[0], ah, kl01[0], kl01[2]);
            mma2(dd[1], ah, kl01[1], kl01[3]);
            mma2(dd[2], ah, kl23[0], kl23[2]);
            mma2(dd[3], ah, kl23[1], kl23[3]);
            mma2(dd[0], al, kh01[0], kh01[2]);
            mma2(dd[1], al, kh01[1], kh01[3]);
            mma2(dd[2], al, kh23[0], kh23[2]);
            mma2(dd[3], al, kh23[1], kh23[3]);
        }
        #pragma unroll
        for (int j = 0; j < 4; ++j)
            #pragma unroll
            for (int c = 0; c < 4; ++c) dd[j][c] *= 0.125f;

        #pragma unroll
        for (int hf = 0; hf < 2; ++hf) {
            const int row = w16 + g + hf*8;
            #pragma unroll
            for (int nt = 0; nt < 4; ++nt)
                *(float2*)(wrow + (size_t)row * NS + k0 + nt*8 + t2)
                    = make_float2(dd[nt][hf*2], dd[nt][hf*2+1]);
            float vm = dd[0][hf*2];
            #pragma unroll
            for (int nt = 0; nt < 4; ++nt)
                vm = fmaxf(vm, fmaxf(dd[nt][hf*2], dd[nt][hf*2+1]));
            vm = fmaxf(vm, __shfl_xor_sync(0xffffffffu, vm, 1));
            vm = fmaxf(vm, __shfl_xor_sync(0xffffffffu, vm, 2));
            float mnew = fmaxf(mr[hf], vm);
            float ps = 0.f;
            #pragma unroll
            for (int nt = 0; nt < 4; ++nt)
                ps += __expf(dd[nt][hf*2] - mnew) + __expf(dd[nt][hf*2+1] - mnew);
            ps += __shfl_xor_sync(0xffffffffu, ps, 1);
            ps += __shfl_xor_sync(0xffffffffu, ps, 2);
            lr[hf] = lr[hf] * __expf(mr[hf] - mnew) + ps;
            mr[hf] = mnew;
        }
    }

    // publish stats
    if ((lane & 3) == 0) {
        #pragma unroll
        for (int hf = 0; hf < 2; ++hf) {
            int row = w16 + g + hf*8;
            mrow[row] = mr[hf];
            lrow[row] = lr[hf];
        }
    }
    __syncthreads();
    if (tid < 128) lrow[tid] = 1.0f / lrow[tid];
    __syncthreads();   // phase barrier: Q/K smem dead after this point

    const float mm0 = mrow[w16 + g],     li0 = lrow[w16 + g];
    const float mm1 = mrow[w16 + g + 8], li1 = lrow[w16 + g + 8];

    // ---- issue V + raw chunk 0 (overlay regions) ----
    {
        const u32 vb = sb, rawb = sb + 20480u;
        CP16(vb + (u32)(vd * PITW + vc) * 2, vthi + (size_t)vd * NS + vc);
        CP16(vb + 5120u + (u32)(vd * PITW + vc) * 2, vtlo + (size_t)vd * NS + vc);
        #pragma unroll
        for (int it = 0; it < 4; ++it) {
            int e = it * 256 + tid, r = e >> 3, seg = e & 7;
            CP16(rawb + (u32)(r * 144 + seg * 16), wrow + (size_t)r * NS + seg * 4);
        }
        CP_COMMIT();
    }

    float da[8][4];
    #pragma unroll
    for (int j = 0; j < 8; ++j)
        #pragma unroll
        for (int c = 0; c < 4; ++c) da[j][c] = 0.f;

    // ================= phase 2: reload raw, normalize, A.V ================
    for (int ch = 0; ch < 64; ++ch) {
        CP_WAIT0();
        __syncthreads();
        if (ch < 63) {
            const u32 nb = (u32)((ch + 1) & 1);
            const u32 vb = sb + nb * 10240u;
            const u32 rawb = sb + 20480u + nb * 18432u;
            const int k0n = (ch + 1) * 32;
            CP16(vb + (u32)(vd * PITW + vc) * 2, vthi + (size_t)vd * NS + k0n + vc);
            CP16(vb + 5120u + (u32)(vd * PITW + vc) * 2, vtlo + (size_t)vd * NS + k0n + vc);
            #pragma unroll
            for (int it = 0; it < 4; ++it) {
                int e = it * 256 + tid, r = e >> 3, seg = e & 7;
                CP16(rawb + (u32)(r * 144 + seg * 16),
                     wrow + (size_t)r * NS + k0n + seg * 4);
            }
            CP_COMMIT();
        }
        const u32 sbV = sb + (u32)(ch & 1) * 10240u;
        const u32 sbVL = sbV + 5120u;
        const float* rawf = (const float*)((const char*)sp + 20480u + (u32)(ch & 1) * 18432u);
        const int k0 = ch * 32;

        // normalize -> w gmem store + A-operand fragments in registers
        u32 awh[2][4], awl[2][4];
        #pragma unroll
        for (int nt = 0; nt < 4; ++nt) {
            #pragma unroll
            for (int hf = 0; hf < 2; ++hf) {
                const int row = w16 + g + hf*8;
                float2 rv = *(const float2*)(rawf + row * 36 + nt*8 + t2);
                const float mm = hf ? mm1 : mm0;
                const float li = hf ? li1 : li0;
                float w0 = __expf(rv.x - mm) * li;
                float w1 = __expf(rv.y - mm) * li;
                *(float2*)(wrow + (size_t)row * NS + k0 + nt*8 + t2)
                    = make_float2(w0, w1);
                u16 h0,l0,h1,l1;
                split1(w0,h0,l0); split1(w1,h1,l1);
                awh[nt >> 1][(nt & 1) * 2 + hf] = pck(h0, h1);
                awl[nt >> 1][(nt & 1) * 2 + hf] = pck(l0, l1);
            }
        }

        // A += W . V (3-term), MMAs interleaved across the accumulator pair
        #pragma unroll
        for (int ks = 0; ks < 2; ++ks) {
            const u32 kb = (u32)(ks * 32);
            #pragma unroll
            for (int pr = 0; pr < 4; ++pr) {
                u32 vh4[4], vl4[4];
                u32 vo = ((u32)(pr*16) + aoff) * (PITW*2) + koff * 2 + kb;
                ldsm4(vh4, sbV + vo);
                ldsm4(vl4, sbVL + vo);
                mma2(da[pr*2],   awh[ks], vh4[0], vh4[2]);
                mma2(da[pr*2+1], awh[ks], vh4[1], vh4[3]);
                mma2(da[pr*2],   awh[ks], vl4[0], vl4[2]);
                mma2(da[pr*2+1], awh[ks], vl4[1], vl4[3]);
                mma2(da[pr*2],   awl[ks], vh4[0], vh4[2]);
                mma2(da[pr*2+1], awl[ks], vh4[1], vh4[3]);
            }
        }
    }

    // epilogue: attn rows -> split bf16 [B*S, H*d]
    #pragma unroll
    for (int hf = 0; hf < 2; ++hf) {
        const int row = w16 + g + hf*8;
        size_t base2 = (size_t)(b*NS + q0 + row) * ND + h * DP;
        #pragma unroll
        for (int nt2 = 0; nt2 < 8; ++nt2) {
            u16 h0,l0,h1,l1;
            split1(da[nt2][hf*2],   h0, l0);
            split1(da[nt2][hf*2+1], h1, l1);
            *(u32*)(g_athi + base2 + nt2*8 + t2) = pck(h0, h1);
            *(u32*)(g_atlo + base2 + nt2*8 + t2) = pck(l0, l1);
        }
    }
}

// =============================================================================
extern "C" void kernel_launch(void* const* d_in, const int* in_sizes, int n_in,
                              void* d_out, int out_size)
{
    const float* q  = (const float*)d_in[0];
    const float* k  = (const float*)d_in[1];
    const float* v  = (const float*)d_in[2];
    const float* Wq = (const float*)d_in[4];
    const float* bq = (const float*)d_in[5];
    const float* Wk = (const float*)d_in[6];
    const float* bk = (const float*)d_in[7];
    const float* Wv = (const float*)d_in[8];
    const float* bv = (const float*)d_in[9];
    const float* Wo = (const float*)d_in[10];
    const float* bo = (const float*)d_in[11];

    float* out     = (float*)d_out;
    float* weights = out + (size_t)MROWS * ND;

    cudaFuncSetAttribute(proj_mma, cudaFuncAttributeMaxDynamicSharedMemorySize, PSM);
    cudaFuncSetAttribute(attn_mma, cudaFuncAttributeMaxDynamicSharedMemorySize, ASMB);

    u16 *inhi, *inlo, *whi, *wlo, *athi, *atlo;
    cudaGetSymbolAddress((void**)&inhi, g_inhi);
    cudaGetSymbolAddress((void**)&inlo, g_inlo);
    cudaGetSymbolAddress((void**)&whi, g_whi);
    cudaGetSymbolAddress((void**)&wlo, g_wlo);
    cudaGetSymbolAddress((void**)&athi, g_athi);
    cudaGetSymbolAddress((void**)&atlo, g_atlo);

    const int NIN = MROWS * ND;   // 4194304
    const int NW  = ND * ND;      // 1048576

    // split q,k,v
    SA a1;
    a1.s[0] = q; a1.s[1] = k; a1.s[2] = v; a1.s[3] = q;
    for (int i = 0; i < 4; ++i) { a1.h[i] = inhi + (size_t)i * NIN; a1.l[i] = inlo + (size_t)i * NIN; }
    a1.h[3] = inhi; a1.l[3] = inlo;
    a1.n = NIN; a1.cnt = 3;
    split_many<<<dim3(NIN / 1024, 1, 3), 256>>>(a1);

    // split Wq,Wk,Wv,Wo
    SA a2;
    a2.s[0] = Wq; a2.s[1] = Wk; a2.s[2] = Wv; a2.s[3] = Wo;
    for (int i = 0; i < 4; ++i) { a2.h[i] = whi + (size_t)i * NW; a2.l[i] = wlo + (size_t)i * NW; }
    a2.n = NW; a2.cnt = 4;
    split_many<<<dim3(NW / 1024, 1, 4), 256>>>(a2);

    dim3 gp(ND / 128, MROWS / 128);
    proj_mma<<<gp, 256, PSM>>>(inhi,              inlo,              whi,          wlo,          bq, nullptr, 0);
    proj_mma<<<gp, 256, PSM>>>(inhi + (size_t)NIN,   inlo + (size_t)NIN,   whi + (size_t)NW,   wlo + (size_t)NW,   bk, nullptr, 1);
    proj_mma<<<gp, 256, PSM>>>(inhi + (size_t)2*NIN, inlo + (size_t)2*NIN, whi + (size_t)2*NW, wlo + (size_t)2*NW, bv, nullptr, 2);

    dim3 ga(NH, NS / 128, NB);
    attn_mma<<<ga, 256, ASMB>>>(weights);

    proj_mma<<<gp, 256, PSM>>>(athi, atlo, whi + (size_t)3*NW, wlo + (size_t)3*NW, bo, out, 3);
}

// round 17
// speedup vs baseline: 1.0754x; 1.0032x over previous
#include <cuda_runtime.h>
#include <cuda_bf16.h>

#define NB 2
#define NS 2048
#define ND 1024
#define NH 16
#define DP 64
#define MROWS (NB*NS)
#define PPIT 40

typedef unsigned int   u32;
typedef unsigned short u16;

// ---------------- device scratch ------------------------------------------
__device__ __align__(16) u16 g_inhi[3*MROWS*ND];
__device__ __align__(16) u16 g_inlo[3*MROWS*ND];
__device__ __align__(16) u16 g_whi[4*ND*ND];
__device__ __align__(16) u16 g_wlo[4*ND*ND];
__device__ __align__(16) u16 g_qhi[NB*NH*NS*DP];
__device__ __align__(16) u16 g_qlo[NB*NH*NS*DP];
__device__ __align__(16) u16 g_khi[NB*NH*NS*DP];
__device__ __align__(16) u16 g_klo[NB*NH*NS*DP];
__device__ __align__(16) u16 g_vthi[NB*NH*DP*NS];  // V^T [B,H,d,S]
__device__ __align__(16) u16 g_vtlo[NB*NH*DP*NS];
__device__ __align__(16) u16 g_athi[MROWS*ND];
__device__ __align__(16) u16 g_atlo[MROWS*ND];

// ---------------- helpers --------------------------------------------------
__device__ __forceinline__ void split1(float x, u16 &h, u16 &l) {
    __nv_bfloat16 hb = __float2bfloat16(x);
    h = __bfloat16_as_ushort(hb);
    l = __bfloat16_as_ushort(__float2bfloat16(x - __bfloat162float(hb)));
}
__device__ __forceinline__ u32 pck(u16 a, u16 b) { return (u32)a | ((u32)b << 16); }

__device__ __forceinline__ void mma2(float* d, const u32* a, u32 b0, u32 b1) {
    asm volatile("mma.sync.aligned.m16n8k16.row.col.f32.bf16.bf16.f32 "
        "{%0,%1,%2,%3}, {%4,%5,%6,%7}, {%8,%9}, {%0,%1,%2,%3};"
        : "+f"(d[0]), "+f"(d[1]), "+f"(d[2]), "+f"(d[3])
        : "r"(a[0]), "r"(a[1]), "r"(a[2]), "r"(a[3]), "r"(b0), "r"(b1));
}
__device__ __forceinline__ void ldsm4(u32* r, u32 addr) {
    asm volatile("ldmatrix.sync.aligned.m8n8.x4.shared.b16 {%0,%1,%2,%3}, [%4];"
        : "=r"(r[0]), "=r"(r[1]), "=r"(r[2]), "=r"(r[3]) : "r"(addr));
}

#define CP16(dst, src) \
    asm volatile("cp.async.ca.shared.global [%0], [%1], 16;" :: "r"(dst), "l"(src))
#define CP_COMMIT() asm volatile("cp.async.commit_group;" ::: "memory")
#define CP_WAIT0()  asm volatile("cp.async.wait_group 0;" ::: "memory")

__device__ __forceinline__ u32 smem_u32(const void* p) {
    u32 a;
    asm("{ .reg .u64 t; cvta.to.shared.u64 t, %1; cvt.u32.u64 %0, t; }"
        : "=r"(a) : "l"(p));
    return a;
}

// =============================================================================
// Split kernel: f32 -> bf16 hi/lo, 7 tensors in one launch.
// =============================================================================
struct SA8 {
    const float* s[7];
    u16* h[7];
    u16* l[7];
    int n[7];
};
__global__ void __launch_bounds__(256)
split8(SA8 a)
{
    int z = blockIdx.z;
    size_t i = ((size_t)blockIdx.x * 256 + threadIdx.x) * 4;
    if (i >= (size_t)a.n[z]) return;
    float4 v = *(const float4*)(a.s[z] + i);
    u16 h0,l0,h1,l1,h2,l2,h3,l3;
    split1(v.x,h0,l0); split1(v.y,h1,l1); split1(v.z,h2,l2); split1(v.w,h3,l3);
    *(uint2*)(a.h[z] + i) = make_uint2(pck(h0,h1), pck(h2,h3));
    *(uint2*)(a.l[z] + i) = make_uint2(pck(l0,l1), pck(l2,l3));
}

// =============================================================================
// Projection GEMM body (bf16 3-term, cp.async BK=32 double buffer, ldmatrix).
// =============================================================================
#define PSM 81920
#define PROJ_ISSUE(kt, bsel) do {                                            \
    const u32 bb = sb + (u32)(bsel) * 40960u;                                \
    const int kk0 = (kt) * 32;                                               \
    _Pragma("unroll")                                                        \
    for (int it = 0; it < 2; ++it) {                                         \
        int idx = tid + it * 256; int r = idx >> 2; int c = (idx & 3) * 8;   \
        u32 doff = (u32)(r * PPIT + c) * 2;                                  \
        CP16(bb + doff,          Xhi + (size_t)(m0 + r) * ND + kk0 + c);     \
        CP16(bb + 10240 + doff,  Xlo + (size_t)(m0 + r) * ND + kk0 + c);     \
        CP16(bb + 20480 + doff,  Whi + (size_t)(n0 + r) * ND + kk0 + c);     \
        CP16(bb + 30720 + doff,  Wlo + (size_t)(n0 + r) * ND + kk0 + c);     \
    }                                                                        \
    CP_COMMIT();                                                             \
} while (0)

__device__ __forceinline__ void
proj_body(const u16* __restrict__ Xhi, const u16* __restrict__ Xlo,
          const u16* __restrict__ Whi, const u16* __restrict__ Wlo,
          const float* __restrict__ bias, float* __restrict__ OutP, int mode)
{
    extern __shared__ u16 sp[];
    const u32 sb = smem_u32(sp);
    const int tid = threadIdx.x, w = tid >> 5, lane = tid & 31;
    const int g = lane >> 2, t2 = (lane & 3) * 2;
    const u32 aoff = (u32)((lane & 7) + ((lane >> 3) & 1) * 8);
    const u32 koff = (u32)((lane >> 4) * 8);
    const int wm = w >> 2, wn = w & 3;
    const int n0 = blockIdx.x * 128, m0 = blockIdx.y * 128;

    float dd[4][4][4];
    #pragma unroll
    for (int i = 0; i < 4; ++i)
        #pragma unroll
        for (int j = 0; j < 4; ++j)
            #pragma unroll
            for (int c = 0; c < 4; ++c) dd[i][j][c] = 0.f;

    PROJ_ISSUE(0, 0);

    for (int kt = 0; kt < 32; ++kt) {
        CP_WAIT0();
        __syncthreads();
        if (kt < 31) PROJ_ISSUE(kt + 1, (kt + 1) & 1);
        const u32 base = sb + (u32)(kt & 1) * 40960u;
        #pragma unroll
        for (int ks = 0; ks < 2; ++ks) {
            const u32 kk = (u32)(ks * 16);
            u32 ah[4][4], al[4][4], bh[2][4], bl[2][4];
            #pragma unroll
            for (int mt = 0; mt < 4; ++mt) {
                u32 ao = ((u32)(wm*64 + mt*16) + aoff) * (PPIT*2) + (kk + koff) * 2;
                ldsm4(ah[mt], base + ao);
                ldsm4(al[mt], base + 10240 + ao);
            }
            #pragma unroll
            for (int pr = 0; pr < 2; ++pr) {
                u32 bo = ((u32)(wn*32 + pr*16) + aoff) * (PPIT*2) + (kk + koff) * 2;
                ldsm4(bh[pr], base + 20480 + bo);
                ldsm4(bl[pr], base + 30720 + bo);
            }
            #pragma unroll
            for (int mt = 0; mt < 4; ++mt)
                #pragma unroll
                for (int pr = 0; pr < 2; ++pr) {
                    mma2(dd[mt][pr*2],   ah[mt], bh[pr][0], bh[pr][2]);
                    mma2(dd[mt][pr*2+1], ah[mt], bh[pr][1], bh[pr][3]);
                }
            #pragma unroll
            for (int mt = 0; mt < 4; ++mt)
                #pragma unroll
                for (int pr = 0; pr < 2; ++pr) {
                    mma2(dd[mt][pr*2],   ah[mt], bl[pr][0], bl[pr][2]);
                    mma2(dd[mt][pr*2+1], ah[mt], bl[pr][1], bl[pr][3]);
                }
            #pragma unroll
            for (int mt = 0; mt < 4; ++mt)
                #pragma unroll
                for (int pr = 0; pr < 2; ++pr) {
                    mma2(dd[mt][pr*2],   al[mt], bh[pr][0], bh[pr][2]);
                    mma2(dd[mt][pr*2+1], al[mt], bh[pr][1], bh[pr][3]);
                }
        }
    }

    #pragma unroll
    for (int mt = 0; mt < 4; ++mt) {
        int r1 = m0 + wm*64 + mt*16 + g, r2 = r1 + 8;
        #pragma unroll
        for (int nt = 0; nt < 4; ++nt) {
            int c = n0 + wn*32 + nt*8 + t2;
            float2 bv = *(const float2*)(bias + c);
            float x0 = dd[mt][nt][0] + bv.x, x1 = dd[mt][nt][1] + bv.y;
            float x2 = dd[mt][nt][2] + bv.x, x3 = dd[mt][nt][3] + bv.y;
            if (mode == 0 || mode == 1) {
                u16* dh = (mode == 0) ? g_qhi : g_khi;
                u16* dl = (mode == 0) ? g_qlo : g_klo;
                int hh = c >> 6, cd = c & 63;
                size_t i1 = ((size_t)((r1 >> 11) * NH + hh) * NS + (r1 & 2047)) * DP + cd;
                size_t i2 = ((size_t)((r2 >> 11) * NH + hh) * NS + (r2 & 2047)) * DP + cd;
                u16 h0,l0,h1,l1;
                split1(x0,h0,l0); split1(x1,h1,l1);
                *(u32*)(dh + i1) = pck(h0,h1); *(u32*)(dl + i1) = pck(l0,l1);
                split1(x2,h0,l0); split1(x3,h1,l1);
                *(u32*)(dh + i2) = pck(h0,h1); *(u32*)(dl + i2) = pck(l0,l1);
            } else if (mode == 2) {
                int hh = c >> 6, cd = c & 63;
                int tok1 = r1 & 2047, tok2 = r2 & 2047;
                size_t b1 = ((size_t)((r1 >> 11) * NH + hh) * DP + cd) * NS + tok1;
                size_t b2 = ((size_t)((r2 >> 11) * NH + hh) * DP + cd) * NS + tok2;
                u16 h0,l0,h1,l1;
                split1(x0,h0,l0); split1(x1,h1,l1);
                g_vthi[b1] = h0; g_vtlo[b1] = l0;
                g_vthi[b1 + NS] = h1; g_vtlo[b1 + NS] = l1;
                split1(x2,h0,l0); split1(x3,h1,l1);
                g_vthi[b2] = h0; g_vtlo[b2] = l0;
                g_vthi[b2 + NS] = h1; g_vtlo[b2 + NS] = l1;
            } else {
                *(float2*)(OutP + (size_t)r1 * ND + c) = make_float2(x0, x1);
                *(float2*)(OutP + (size_t)r2 * ND + c) = make_float2(x2, x3);
            }
        }
    }
}

struct PJ3 {
    const u16 *xh[3], *xl[3], *wh[3], *wl[3];
    const float* bias[3];
};
__global__ void __launch_bounds__(256, 2)
proj_qkv(PJ3 p)
{
    int z = blockIdx.z;
    proj_body(p.xh[z], p.xl[z], p.wh[z], p.wl[z], p.bias[z], nullptr, z);
}
__global__ void __launch_bounds__(256, 2)
proj_out(const u16* __restrict__ Xhi, const u16* __restrict__ Xlo,
         const u16* __restrict__ Whi, const u16* __restrict__ Wlo,
         const float* __restrict__ bias, float* __restrict__ OutP)
{
    proj_body(Xhi, Xlo, Whi, Wlo, bias, OutP, 3);
}

// =============================================================================
// Fused attention v6: store-raw + register W-fragments, 64-key chunks.
// smem BYTE map:
//  phase 1: QH 0..18432, QL 18432..36864,
//           K bufs 36864 + i*18432 {KH 9216 | KL +9216}, i=0..1 -> 73728
//  phase 2 (overlaid): V bufs i*18432 {VH 9216 | VL +9216} -> 36864
//           raw bufs 36864 + i*34816 (128 rows x 68 f32)   -> 106496
//  stats @106496 (mrow 128 f32, lrow 128 f32) -> ASMB 107520
// =============================================================================
#define ASMB 107520
#define AK_ISSUE(ck, st) do {                                                \
    const u32 kb_ = sb + 36864u + (u32)(st) * 18432u;                        \
    const int k0n_ = (ck) * 64;                                              \
    u32 o1_ = (u32)(kr * 72 + kc16) * 2, o2_ = o1_ + 16u;                    \
    CP16(kb_ + o1_, khi + (size_t)(k0n_ + kr) * DP + kc16);                  \
    CP16(kb_ + o2_, khi + (size_t)(k0n_ + kr) * DP + kc16 + 8);              \
    CP16(kb_ + 9216u + o1_, klo + (size_t)(k0n_ + kr) * DP + kc16);          \
    CP16(kb_ + 9216u + o2_, klo + (size_t)(k0n_ + kr) * DP + kc16 + 8);      \
    CP_COMMIT();                                                             \
} while (0)

#define AVR_ISSUE(ck, st) do {                                               \
    const u32 vb_ = sb + (u32)(st) * 18432u;                                 \
    const u32 rb_ = sb + 36864u + (u32)(st) * 34816u;                        \
    const int k0n_ = (ck) * 64;                                              \
    u32 o1_ = (u32)(vd * 72 + vc16) * 2, o2_ = o1_ + 16u;                    \
    CP16(vb_ + o1_, vthi + (size_t)vd * NS + k0n_ + vc16);                   \
    CP16(vb_ + o2_, vthi + (size_t)vd * NS + k0n_ + vc16 + 8);               \
    CP16(vb_ + 9216u + o1_, vtlo + (size_t)vd * NS + k0n_ + vc16);           \
    CP16(vb_ + 9216u + o2_, vtlo + (size_t)vd * NS + k0n_ + vc16 + 8);       \
    _Pragma("unroll")                                                        \
    for (int it_ = 0; it_ < 8; ++it_) {                                      \
        int e_ = it_ * 256 + tid, r_ = e_ >> 4, sg_ = e_ & 15;               \
        CP16(rb_ + (u32)(r_ * 272 + sg_ * 16),                               \
             wrow + (size_t)r_ * NS + k0n_ + sg_ * 4);                       \
    }                                                                        \
    CP_COMMIT();                                                             \
} while (0)

__global__ void __launch_bounds__(256, 2)
attn_mma(float* __restrict__ wbuf)
{
    extern __shared__ u16 sp[];
    u16* QH = sp;
    u16* QL = sp + 9216;
    float* mrow = (float*)(sp + 53248);   // byte 106496
    float* lrow = mrow + 128;

    const u32 sb = smem_u32(sp);
    const int tid = threadIdx.x, w = tid >> 5, lane = tid & 31;
    const int g = lane >> 2, t2 = (lane & 3) * 2;
    const u32 aoff = (u32)((lane & 7) + ((lane >> 3) & 1) * 8);
    const u32 koff = (u32)((lane >> 4) * 8);
    const int h = blockIdx.x, qt = blockIdx.y, b = blockIdx.z;
    const int q0 = qt * 128;
    const int w16 = w * 16;
    const size_t hb = (size_t)(b * NH + h) * NS;
    const u16* qhi = g_qhi + (hb + q0) * DP;
    const u16* qlo = g_qlo + (hb + q0) * DP;
    const u16* khi = g_khi + hb * DP;
    const u16* klo = g_klo + hb * DP;
    const u16* vthi = g_vthi + (size_t)(b * NH + h) * DP * NS;
    const u16* vtlo = g_vtlo + (size_t)(b * NH + h) * DP * NS;
    float* wrow = wbuf + (hb + q0) * NS;

    // Q tile resident (phase 1 only), pitch 72
    #pragma unroll
    for (int it = 0; it < 4; ++it) {
        int e = it * 256 + tid, r = e >> 3, c8 = (e & 7) * 8;
        *(uint4*)(QH + r * 72 + c8) = *(const uint4*)(qhi + (size_t)r * DP + c8);
        *(uint4*)(QL + r * 72 + c8) = *(const uint4*)(qlo + (size_t)r * DP + c8);
    }

    const int kr = tid >> 2, kc16 = (tid & 3) * 16;   // K copy: 64 rows x 64 d
    const int vd = tid >> 2, vc16 = (tid & 3) * 16;   // V copy: 64 d x 64 keys

    const u32 aQ = ((u32)w16 + aoff) * 144u + koff * 2;

    AK_ISSUE(0, 0);

    float mr[2] = {-1e30f, -1e30f}, lr[2] = {0.f, 0.f};

    // ================= phase 1: QK^T once -> raw store + stats =============
    for (int kt = 0; kt < 32; ++kt) {
        CP_WAIT0();
        __syncthreads();
        if (kt < 31) AK_ISSUE(kt + 1, (kt + 1) & 1);
        const u32 sbK = sb + 36864u + (u32)(kt & 1) * 18432u;
        const u32 sbKL = sbK + 9216u;
        const int k0 = kt * 64;

        float dd[8][4];
        #pragma unroll
        for (int j = 0; j < 8; ++j)
            #pragma unroll
            for (int c = 0; c < 4; ++c) dd[j][c] = 0.f;

        #pragma unroll
        for (int ks = 0; ks < 4; ++ks) {
            const u32 kb = (u32)(ks * 32);
            u32 ah[4], al[4], kh[4][4], kl[4][4];
            ldsm4(ah, sb + aQ + kb);
            ldsm4(al, sb + 18432u + aQ + kb);
            #pragma unroll
            for (int kp = 0; kp < 4; ++kp) {
                u32 bo = ((u32)(kp*16) + aoff) * 144u + koff * 2 + kb;
                ldsm4(kh[kp], sbK + bo);
                ldsm4(kl[kp], sbKL + bo);
            }
            #pragma unroll
            for (int kp = 0; kp < 4; ++kp) {
                mma2(dd[kp*2],   ah, kh[kp][0], kh[kp][2]);
                mma2(dd[kp*2+1], ah, kh[kp][1], kh[kp][3]);
            }
            #pragma unroll
            for (int kp = 0; kp < 4; ++kp) {
                mma2(dd[kp*2],   ah, kl[kp][0], kl[kp][2]);
                mma2(dd[kp*2+1], ah, kl[kp][1], kl[kp][3]);
            }
            #pragma unroll
            for (int kp = 0; kp < 4; ++kp) {
                mma2(dd[kp*2],   al, kh[kp][0], kh[kp][2]);
                mma2(dd[kp*2+1], al, kh[kp][1], kh[kp][3]);
            }
        }
        #pragma unroll
        for (int j = 0; j < 8; ++j)
            #pragma unroll
            for (int c = 0; c < 4; ++c) dd[j][c] *= 0.125f;

        #pragma unroll
        for (int hf = 0; hf < 2; ++hf) {
            const int row = w16 + g + hf*8;
            #pragma unroll
            for (int nt = 0; nt < 8; ++nt)
                *(float2*)(wrow + (size_t)row * NS + k0 + nt*8 + t2)
                    = make_float2(dd[nt][hf*2], dd[nt][hf*2+1]);
            float vm = dd[0][hf*2];
            #pragma unroll
            for (int nt = 0; nt < 8; ++nt)
                vm = fmaxf(vm, fmaxf(dd[nt][hf*2], dd[nt][hf*2+1]));
            vm = fmaxf(vm, __shfl_xor_sync(0xffffffffu, vm, 1));
            vm = fmaxf(vm, __shfl_xor_sync(0xffffffffu, vm, 2));
            float mnew = fmaxf(mr[hf], vm);
            float ps = 0.f;
            #pragma unroll
            for (int nt = 0; nt < 8; ++nt)
                ps += __expf(dd[nt][hf*2] - mnew) + __expf(dd[nt][hf*2+1] - mnew);
            ps += __shfl_xor_sync(0xffffffffu, ps, 1);
            ps += __shfl_xor_sync(0xffffffffu, ps, 2);
            lr[hf] = lr[hf] * __expf(mr[hf] - mnew) + ps;
            mr[hf] = mnew;
        }
    }

    // publish stats
    if ((lane & 3) == 0) {
        #pragma unroll
        for (int hf = 0; hf < 2; ++hf) {
            int row = w16 + g + hf*8;
            mrow[row] = mr[hf];
            lrow[row] = lr[hf];
        }
    }
    __syncthreads();
    if (tid < 128) lrow[tid] = 1.0f / lrow[tid];
    __syncthreads();   // Q/K smem dead after this point

    const float mm0 = mrow[w16 + g],     li0 = lrow[w16 + g];
    const float mm1 = mrow[w16 + g + 8], li1 = lrow[w16 + g + 8];

    AVR_ISSUE(0, 0);

    float da[8][4];
    #pragma unroll
    for (int j = 0; j < 8; ++j)
        #pragma unroll
        for (int c = 0; c < 4; ++c) da[j][c] = 0.f;

    // ================= phase 2: reload raw, normalize, A.V ================
    for (int ch = 0; ch < 32; ++ch) {
        CP_WAIT0();
        __syncthreads();
        if (ch < 31) AVR_ISSUE(ch + 1, (ch + 1) & 1);
        const u32 sbV = sb + (u32)(ch & 1) * 18432u;
        const u32 sbVL = sbV + 9216u;
        const float* rawf = (const float*)((const char*)sp + 36864u + (u32)(ch & 1) * 34816u);
        const int k0 = ch * 64;

        #pragma unroll
        for (int ks = 0; ks < 4; ++ks) {
            // build W frags for keys ks*16..+15 (normalize + store + split)
            u32 awh[4], awl[4];
            #pragma unroll
            for (int half = 0; half < 2; ++half) {
                const int nt = ks*2 + half;
                #pragma unroll
                for (int hf = 0; hf < 2; ++hf) {
                    const int row = w16 + g + hf*8;
                    float2 rv = *(const float2*)(rawf + row * 68 + nt*8 + t2);
                    const float mm = hf ? mm1 : mm0;
                    const float li = hf ? li1 : li0;
                    float w0 = __expf(rv.x - mm) * li;
                    float w1 = __expf(rv.y - mm) * li;
                    *(float2*)(wrow + (size_t)row * NS + k0 + nt*8 + t2)
                        = make_float2(w0, w1);
                    u16 h0,l0,h1,l1;
                    split1(w0,h0,l0); split1(w1,h1,l1);
                    awh[half*2 + hf] = pck(h0, h1);
                    awl[half*2 + hf] = pck(l0, l1);
                }
            }
            // A += W . V (3-term) over all 64 d columns
            #pragma unroll
            for (int pr = 0; pr < 4; ++pr) {
                u32 vh4[4], vl4[4];
                u32 vo = ((u32)(pr*16) + aoff) * 144u + ((u32)(ks*16) + koff) * 2;
                ldsm4(vh4, sbV + vo);
                ldsm4(vl4, sbVL + vo);
                mma2(da[pr*2],   awh, vh4[0], vh4[2]);
                mma2(da[pr*2+1], awh, vh4[1], vh4[3]);
                mma2(da[pr*2],   awh, vl4[0], vl4[2]);
                mma2(da[pr*2+1], awh, vl4[1], vl4[3]);
                mma2(da[pr*2],   awl, vh4[0], vh4[2]);
                mma2(da[pr*2+1], awl, vh4[1], vh4[3]);
            }
        }
    }

    // epilogue: attn rows -> split bf16 [B*S, H*d]
    #pragma unroll
    for (int hf = 0; hf < 2; ++hf) {
        const int row = w16 + g + hf*8;
        size_t base2 = (size_t)(b*NS + q0 + row) * ND + h * DP;
        #pragma unroll
        for (int nt2 = 0; nt2 < 8; ++nt2) {
            u16 h0,l0,h1,l1;
            split1(da[nt2][hf*2],   h0, l0);
            split1(da[nt2][hf*2+1], h1, l1);
            *(u32*)(g_athi + base2 + nt2*8 + t2) = pck(h0, h1);
            *(u32*)(g_atlo + base2 + nt2*8 + t2) = pck(l0, l1);
        }
    }
}

// =============================================================================
extern "C" void kernel_launch(void* const* d_in, const int* in_sizes, int n_in,
                              void* d_out, int out_size)
{
    const float* q  = (const float*)d_in[0];
    const float* k  = (const float*)d_in[1];
    const float* v  = (const float*)d_in[2];
    const float* Wq = (const float*)d_in[4];
    const float* bq = (const float*)d_in[5];
    const float* Wk = (const float*)d_in[6];
    const float* bk = (const float*)d_in[7];
    const float* Wv = (const float*)d_in[8];
    const float* bv = (const float*)d_in[9];
    const float* Wo = (const float*)d_in[10];
    const float* bo = (const float*)d_in[11];

    float* out     = (float*)d_out;
    float* weights = out + (size_t)MROWS * ND;

    cudaFuncSetAttribute(proj_qkv, cudaFuncAttributeMaxDynamicSharedMemorySize, PSM);
    cudaFuncSetAttribute(proj_out, cudaFuncAttributeMaxDynamicSharedMemorySize, PSM);
    cudaFuncSetAttribute(attn_mma, cudaFuncAttributeMaxDynamicSharedMemorySize, ASMB);

    u16 *inhi, *inlo, *whi, *wlo, *athi, *atlo;
    cudaGetSymbolAddress((void**)&inhi, g_inhi);
    cudaGetSymbolAddress((void**)&inlo, g_inlo);
    cudaGetSymbolAddress((void**)&whi, g_whi);
    cudaGetSymbolAddress((void**)&wlo, g_wlo);
    cudaGetSymbolAddress((void**)&athi, g_athi);
    cudaGetSymbolAddress((void**)&atlo, g_atlo);

    const int NIN = MROWS * ND;   // 4194304
    const int NW  = ND * ND;      // 1048576

    // one split launch: q,k,v + 4 weight matrices
    SA8 a;
    a.s[0] = q;  a.s[1] = k;  a.s[2] = v;
    a.s[3] = Wq; a.s[4] = Wk; a.s[5] = Wv; a.s[6] = Wo;
    for (int i = 0; i < 3; ++i) {
        a.h[i] = inhi + (size_t)i * NIN; a.l[i] = inlo + (size_t)i * NIN; a.n[i] = NIN;
    }
    for (int i = 0; i < 4; ++i) {
        a.h[3+i] = whi + (size_t)i * NW; a.l[3+i] = wlo + (size_t)i * NW; a.n[3+i] = NW;
    }
    split8<<<dim3(NIN / 1024, 1, 7), 256>>>(a);

    // fused Q/K/V projections: one launch, z = which projection
    PJ3 p;
    for (int i = 0; i < 3; ++i) {
        p.xh[i] = inhi + (size_t)i * NIN;
        p.xl[i] = inlo + (size_t)i * NIN;
        p.wh[i] = whi + (size_t)i * NW;
        p.wl[i] = wlo + (size_t)i * NW;
    }
    p.bias[0] = bq; p.bias[1] = bk; p.bias[2] = bv;
    proj_qkv<<<dim3(ND / 128, MROWS / 128, 3), 256, PSM>>>(p);

    dim3 ga(NH, NS / 128, NB);
    attn_mma<<<ga, 256, ASMB>>>(weights);

    proj_out<<<dim3(ND / 128, MROWS / 128), 256, PSM>>>(
        athi, atlo, whi + (size_t)3*NW, wlo + (size_t)3*NW, bo, out);
}